// round 1
// baseline (speedup 1.0000x reference)
#include <cuda_runtime.h>
#include <cstdint>

// Problem constants
#define BB   2
#define JJ   24
#define DD   32
#define NV   32768           // 32*32*32
#define PX2D (JJ*DD)         // 768

// ---------------------------------------------------------------------------
// Scratch (device globals; no allocation allowed)
// ---------------------------------------------------------------------------
__device__ float g_x2d[BB*7*PX2D];   // [dual(0..4), evalop1(5), g(6)]
__device__ float g_h2a[BB*32*PX2D];
__device__ float g_h2b[BB*32*PX2D];
__device__ float g_y3d[BB*6*NV];     // [primal(0..4), evalop2(5)]
__device__ float g_h3a[BB*32*NV];
__device__ float g_h3b[BB*32*NV];
__device__ float g_f  [BB*NV];       // Fortran-flattened primal channel 1

// ---------------------------------------------------------------------------
// Init: dual -> x2d[0..4], g -> x2d[6], primal -> y3d[0..4]
// ---------------------------------------------------------------------------
__global__ void init_kernel(const float* __restrict__ dual,
                            const float* __restrict__ gg,
                            const float* __restrict__ primal) {
    int i = blockIdx.x * blockDim.x + threadIdx.x;
    if (i < BB*5*NV) {
        int b = i / (5*NV); int r = i % (5*NV); int c = r / NV; int v = r % NV;
        g_y3d[(size_t)(b*6 + c)*NV + v] = primal[i];
    }
    if (i < BB*5*PX2D) {
        int b = i / (5*PX2D); int r = i % (5*PX2D); int c = r / PX2D; int p = r % PX2D;
        g_x2d[(size_t)(b*7 + c)*PX2D + p] = dual[i];
    }
    if (i < BB*PX2D) {
        int b = i / PX2D; int p = i % PX2D;
        g_x2d[(size_t)(b*7 + 6)*PX2D + p] = gg[i];
    }
}

// ---------------------------------------------------------------------------
// Fortran-order gather: f[b, (x*32+y)*32+z] = primal_ch1[b, z, y, x]
// ---------------------------------------------------------------------------
__global__ void gather_f_kernel() {
    int i = blockIdx.x * blockDim.x + threadIdx.x;
    if (i >= BB*NV) return;
    int b = i / NV, v = i % NV;
    int z = v & 31, y = (v >> 5) & 31, x = v >> 10;
    g_f[i] = g_y3d[(size_t)(b*6 + 1)*NV + (z*32 + y)*32 + x];
}

// ---------------------------------------------------------------------------
// evalop1[b,j,d] = sum_v An[b,j,d,v] * f[b,v]   (one block per row, 1536 rows)
// Writes into x2d channel 5. An streamed with __ldcs (201 MB, no L2 reuse).
// ---------------------------------------------------------------------------
__global__ void evalop1_kernel(const float* __restrict__ An) {
    const int row = blockIdx.x;                 // (b*J + j)*D + d
    const int b   = row / PX2D;
    const float4* a = reinterpret_cast<const float4*>(An) + (size_t)row * (NV/4);
    const float4* f = reinterpret_cast<const float4*>(g_f) + (size_t)b * (NV/4);
    float acc = 0.f;
    #pragma unroll 4
    for (int i = threadIdx.x; i < NV/4; i += 256) {
        float4 av = __ldcs(a + i);
        float4 fv = f[i];
        acc = fmaf(av.x, fv.x, acc);
        acc = fmaf(av.y, fv.y, acc);
        acc = fmaf(av.z, fv.z, acc);
        acc = fmaf(av.w, fv.w, acc);
    }
    #pragma unroll
    for (int off = 16; off; off >>= 1) acc += __shfl_down_sync(0xffffffffu, acc, off);
    __shared__ float red[8];
    if ((threadIdx.x & 31) == 0) red[threadIdx.x >> 5] = acc;
    __syncthreads();
    if (threadIdx.x == 0) {
        float s = 0.f;
        #pragma unroll
        for (int i = 0; i < 8; i++) s += red[i];
        g_x2d[(size_t)(b*7 + 5)*PX2D + (row % PX2D)] = s;
    }
}

// ---------------------------------------------------------------------------
// 2D conv 3x3 SAME over (J=24, D=32). One block per (px-chunk, co, b).
// ---------------------------------------------------------------------------
template<int CIN, bool PRELU, bool RES>
__global__ void conv2d_kernel(const float* __restrict__ in, int in_ct,
                              const float* __restrict__ w,
                              const float* __restrict__ bias,
                              const float* __restrict__ alpha,
                              float* __restrict__ out, int out_ct) {
    const int b  = blockIdx.z;
    const int co = blockIdx.y;
    const int p  = blockIdx.x * 256 + threadIdx.x;   // 0..767
    __shared__ float sw[CIN*9];
    for (int i = threadIdx.x; i < CIN*9; i += 256) sw[i] = w[co*CIN*9 + i];
    __syncthreads();
    const int j = p / 32, d = p % 32;
    const float* xb = in + (size_t)b * in_ct * PX2D;
    float acc = bias[co];
    #pragma unroll 4
    for (int ci = 0; ci < CIN; ci++) {
        const float* xc = xb + ci * PX2D;
        #pragma unroll
        for (int kj = 0; kj < 3; kj++) {
            int jjj = j + kj - 1;
            if (jjj < 0 || jjj >= JJ) continue;
            #pragma unroll
            for (int kd = 0; kd < 3; kd++) {
                int ddd = d + kd - 1;
                if (ddd < 0 || ddd >= DD) continue;
                acc = fmaf(sw[ci*9 + kj*3 + kd], xc[jjj*32 + ddd], acc);
            }
        }
    }
    if (PRELU) { float a = alpha[0]; acc = acc >= 0.f ? acc : a * acc; }
    float* o = out + (size_t)(b*out_ct + co)*PX2D + p;
    if (RES) *o += acc; else *o = acc;
}

// ---------------------------------------------------------------------------
// adjoint: back[b,v] = sum_{j,d} A[b,j,v,d] * dual0[b,j,d]
// One warp per v (8 v per block). Writes evalop2 into y3d channel 5 with the
// inverse Fortran mapping.
// ---------------------------------------------------------------------------
__global__ void adjoint_kernel(const float* __restrict__ A) {
    __shared__ float sd[PX2D];
    const int b  = blockIdx.x / (NV/8);
    const int v0 = (blockIdx.x % (NV/8)) * 8;
    for (int i = threadIdx.x; i < PX2D; i += 256)
        sd[i] = g_x2d[(size_t)(b*7 + 0)*PX2D + i];
    __syncthreads();
    const int wrp = threadIdx.x >> 5, lane = threadIdx.x & 31;
    const int v = v0 + wrp;
    const float* Ab = A + (size_t)b * JJ * NV * DD;
    float acc = 0.f;
    #pragma unroll
    for (int j = 0; j < JJ; j++)
        acc = fmaf(__ldcs(Ab + ((size_t)j*NV + v)*DD + lane), sd[j*DD + lane], acc);
    #pragma unroll
    for (int off = 16; off; off >>= 1) acc += __shfl_down_sync(0xffffffffu, acc, off);
    if (lane == 0) {
        int z = v & 31, y = (v >> 5) & 31, x = v >> 10;
        g_y3d[(size_t)(b*6 + 5)*NV + (z*32 + y)*32 + x] = acc;
    }
}

// ---------------------------------------------------------------------------
// 3D conv 3x3x3 SAME over 32^3.
// Block = one z-plane slice (YR rows) x COPB output channels.
// Thread = XPT consecutive x outputs for COPB channels (acc in registers).
// Input channel tile staged in smem (stride 35 -> conflict-free LDS).
// ---------------------------------------------------------------------------
template<int CIN, int COPB, int XPT, int YR, bool PRELU, bool RES>
__global__ void __launch_bounds__((32/XPT)*YR)
conv3d_kernel(const float* __restrict__ in, int in_ct,
              const float* __restrict__ w,
              const float* __restrict__ bias,
              const float* __restrict__ alpha,
              float* __restrict__ out, int out_ct) {
    constexpr int XG    = 32 / XPT;
    constexpr int NT    = XG * YR;
    constexpr int TROWS = YR + 2;
    constexpr int TW    = 35;               // 34 used cols + 1 pad (bank-conflict-free)
    constexpr int YSPL  = 32 / YR;

    __shared__ float tile[3 * TROWS * TW];
    __shared__ float swt[COPB * CIN * 27];

    const int b   = blockIdx.z;
    const int z   = blockIdx.y;
    const int cg  = blockIdx.x / YSPL;
    const int y0  = (blockIdx.x % YSPL) * YR;
    const int tid = threadIdx.x;

    for (int i = tid; i < COPB*CIN*27; i += NT)
        swt[i] = w[(size_t)cg*COPB*CIN*27 + i];

    const int xg = tid % XG;
    const int ly = tid / XG;
    const int x0 = xg * XPT;
    const int y  = y0 + ly;

    float acc[COPB][XPT];
    #pragma unroll
    for (int c = 0; c < COPB; c++)
        #pragma unroll
        for (int xi = 0; xi < XPT; xi++) acc[c][xi] = 0.f;

    for (int ci = 0; ci < CIN; ci++) {
        __syncthreads();
        const float* inc = in + (size_t)(b*in_ct + ci) * NV;
        // load padded 3 x (YR+2) x 34 tile for this input channel
        for (int i = tid; i < 3*TROWS*34; i += NT) {
            int kz  = i / (TROWS*34);
            int rem = i % (TROWS*34);
            int ry  = rem / 34, rx = rem % 34;
            int zz = z + kz - 1, yy = y0 + ry - 1, xx = rx - 1;
            float v = 0.f;
            if (zz >= 0 && zz < 32 && yy >= 0 && yy < 32 && xx >= 0 && xx < 32)
                v = inc[(zz*32 + yy)*32 + xx];
            tile[(kz*TROWS + ry)*TW + rx] = v;
        }
        __syncthreads();

        #pragma unroll
        for (int kz = 0; kz < 3; kz++) {
            #pragma unroll
            for (int ky = 0; ky < 3; ky++) {
                float inr[XPT + 2];
                const float* trow = &tile[(kz*TROWS + (ly + ky))*TW + x0];
                #pragma unroll
                for (int t = 0; t < XPT + 2; t++) inr[t] = trow[t];
                #pragma unroll
                for (int co = 0; co < COPB; co++) {
                    #pragma unroll
                    for (int kx = 0; kx < 3; kx++) {
                        float wv = swt[(co*CIN + ci)*27 + kz*9 + ky*3 + kx];
                        #pragma unroll
                        for (int xi = 0; xi < XPT; xi++)
                            acc[co][xi] = fmaf(wv, inr[xi + kx], acc[co][xi]);
                    }
                }
            }
        }
    }

    const float a = PRELU ? alpha[0] : 0.f;
    #pragma unroll
    for (int co = 0; co < COPB; co++) {
        const float bv = bias[cg*COPB + co];
        float* op = out + (size_t)(b*out_ct + cg*COPB + co)*NV + (z*32 + y)*32 + x0;
        #pragma unroll
        for (int xi = 0; xi < XPT; xi++) {
            float r = acc[co][xi] + bv;
            if (PRELU) r = r >= 0.f ? r : a * r;
            if (RES) op[xi] += r; else op[xi] = r;
        }
    }
}

// ---------------------------------------------------------------------------
// Output: primal channel 0
// ---------------------------------------------------------------------------
__global__ void out_kernel(float* __restrict__ out) {
    int i = blockIdx.x * blockDim.x + threadIdx.x;
    if (i >= BB*NV) return;
    int b = i / NV, v = i % NV;
    out[i] = g_y3d[(size_t)b*6*NV + v];
}

// ---------------------------------------------------------------------------
extern "C" void kernel_launch(void* const* d_in, const int* in_sizes, int n_in,
                              void* d_out, int out_size) {
    (void)in_sizes; (void)n_in; (void)out_size;
    const float* dual   = (const float*)d_in[0];
    const float* primal = (const float*)d_in[1];
    const float* g      = (const float*)d_in[2];
    const float* An     = (const float*)d_in[3];
    const float* A      = (const float*)d_in[4];
    const float* dw1 = (const float*)d_in[5];  const float* db1 = (const float*)d_in[6];
    const float* da1 = (const float*)d_in[7];
    const float* dw2 = (const float*)d_in[8];  const float* db2 = (const float*)d_in[9];
    const float* da2 = (const float*)d_in[10];
    const float* dw3 = (const float*)d_in[11]; const float* db3 = (const float*)d_in[12];
    const float* pw1 = (const float*)d_in[13]; const float* pb1 = (const float*)d_in[14];
    const float* pa1 = (const float*)d_in[15];
    const float* pw2 = (const float*)d_in[16]; const float* pb2 = (const float*)d_in[17];
    const float* pa2 = (const float*)d_in[18];
    const float* pw3 = (const float*)d_in[19]; const float* pb3 = (const float*)d_in[20];

    float *px2d, *ph2a, *ph2b, *py3d, *ph3a, *ph3b;
    cudaGetSymbolAddress((void**)&px2d, g_x2d);
    cudaGetSymbolAddress((void**)&ph2a, g_h2a);
    cudaGetSymbolAddress((void**)&ph2b, g_h2b);
    cudaGetSymbolAddress((void**)&py3d, g_y3d);
    cudaGetSymbolAddress((void**)&ph3a, g_h3a);
    cudaGetSymbolAddress((void**)&ph3b, g_h3b);

    init_kernel<<<(BB*5*NV + 255)/256, 256>>>(dual, g, primal);

    for (int k = 0; k < 10; k++) {
        // --- dual space ---
        gather_f_kernel<<<(BB*NV + 255)/256, 256>>>();
        evalop1_kernel<<<BB*JJ*DD, 256>>>(An);

        conv2d_kernel<7, true, false><<<dim3(3, 32, BB), 256>>>(
            px2d, 7, dw1 + (size_t)k*32*7*9, db1 + k*32, da1 + k, ph2a, 32);
        conv2d_kernel<32, true, false><<<dim3(3, 32, BB), 256>>>(
            ph2a, 32, dw2 + (size_t)k*32*32*9, db2 + k*32, da2 + k, ph2b, 32);
        conv2d_kernel<32, false, true><<<dim3(3, 5, BB), 256>>>(
            ph2b, 32, dw3 + (size_t)k*5*32*9, db3 + k*5, nullptr, px2d, 7);

        // --- adjoint ---
        adjoint_kernel<<<BB*NV/8, 256>>>(A);

        // --- primal space ---
        conv3d_kernel<6, 8, 8, 32, true, false><<<dim3(4, 32, BB), 128>>>(
            py3d, 6, pw1 + (size_t)k*32*6*27, pb1 + k*32, pa1 + k, ph3a, 32);
        conv3d_kernel<32, 8, 8, 32, true, false><<<dim3(4, 32, BB), 128>>>(
            ph3a, 32, pw2 + (size_t)k*32*32*27, pb2 + k*32, pa2 + k, ph3b, 32);
        conv3d_kernel<32, 5, 4, 16, false, true><<<dim3(2, 32, BB), 128>>>(
            ph3b, 32, pw3 + (size_t)k*5*32*27, pb3 + k*5, nullptr, py3d, 6);
    }

    out_kernel<<<(BB*NV + 255)/256, 256>>>((float*)d_out);
}